// round 1
// baseline (speedup 1.0000x reference)
#include <cuda_runtime.h>
#include <math.h>

#define BB 16
#define NN 1024
#define FIN 64
#define HH 256
#define NEGV (-9e15f)
#define LALPHA 0.2f

// ---------------- scratch (device globals: no allocation allowed) ----------
__device__ __align__(256) float g_x[BB * NN * HH];     // 16 MB
__device__ __align__(256) float g_h[BB * NN * HH];     // 16 MB
__device__ __align__(256) float g_s1[BB * NN];
__device__ __align__(256) float g_s2[BB * NN];
__device__ __align__(256) float g_m[BB * NN];
__device__ __align__(256) float g_linv[BB * NN];
__device__ __align__(256) float g_sum[BB * HH];
__device__ __align__(256) float g_max[BB * HH];

// ---------------- generic tiled SGEMM: C = A[M,K] @ B[K,Nc] (+bias) --------
// BM=128, BN=64, BK=16, 256 threads, micro-tile 8x4.
__global__ void __launch_bounds__(256) sgemm_kernel(
    const float* __restrict__ A, const float* __restrict__ Bw,
    const float* __restrict__ bias, float* __restrict__ C,
    int M, int K, int Nc)
{
    __shared__ float As[16][128];   // transposed A tile
    __shared__ float Bs[16][64];

    int tid = threadIdx.x;
    int tx = tid & 15;        // 0..15 -> col group (4 cols)
    int ty = tid >> 4;        // 0..15 -> row group (8 rows)
    int m0 = blockIdx.y * 128;
    int n0 = blockIdx.x * 64;

    float acc[8][4];
#pragma unroll
    for (int r = 0; r < 8; r++)
#pragma unroll
        for (int c = 0; c < 4; c++) acc[r][c] = 0.f;

    for (int k0 = 0; k0 < K; k0 += 16) {
        // load A tile 128x16 (transposed into As[k][m])
#pragma unroll
        for (int t = 0; t < 2; t++) {
            int lin = tid * 2 + t;            // 0..511
            int r = lin >> 2;                 // 0..127
            int c4 = (lin & 3) * 4;           // 0,4,8,12
            float4 v = *(const float4*)(A + (size_t)(m0 + r) * K + k0 + c4);
            As[c4 + 0][r] = v.x;
            As[c4 + 1][r] = v.y;
            As[c4 + 2][r] = v.z;
            As[c4 + 3][r] = v.w;
        }
        // load B tile 16x64
        {
            int r = tid >> 4;
            int c4 = (tid & 15) * 4;
            *(float4*)&Bs[r][c4] =
                *(const float4*)(Bw + (size_t)(k0 + r) * Nc + n0 + c4);
        }
        __syncthreads();

#pragma unroll
        for (int k = 0; k < 16; k++) {
            float4 a0 = *(float4*)&As[k][ty * 8];
            float4 a1 = *(float4*)&As[k][ty * 8 + 4];
            float4 bv = *(float4*)&Bs[k][tx * 4];
            float av[8] = {a0.x, a0.y, a0.z, a0.w, a1.x, a1.y, a1.z, a1.w};
            float bvv[4] = {bv.x, bv.y, bv.z, bv.w};
#pragma unroll
            for (int r = 0; r < 8; r++)
#pragma unroll
                for (int c = 0; c < 4; c++)
                    acc[r][c] = fmaf(av[r], bvv[c], acc[r][c]);
        }
        __syncthreads();
    }

#pragma unroll
    for (int r = 0; r < 8; r++) {
        int row = m0 + ty * 8 + r;
        float4 v;
        v.x = acc[r][0]; v.y = acc[r][1]; v.z = acc[r][2]; v.w = acc[r][3];
        if (bias) {
            const float* bp = bias + n0 + tx * 4;
            v.x += bp[0]; v.y += bp[1]; v.z += bp[2]; v.w += bp[3];
        }
        *(float4*)(C + (size_t)row * Nc + n0 + tx * 4) = v;
    }
}

// ---------------- s1 = h . a1, s2 = h . a2 (one warp per row) --------------
__global__ void rowdot_kernel(const float* __restrict__ h,
                              const float* __restrict__ a1,
                              const float* __restrict__ a2)
{
    int warp = (blockIdx.x * blockDim.x + threadIdx.x) >> 5;
    int lane = threadIdx.x & 31;
    if (warp >= BB * NN) return;

    const float* hr = h + (size_t)warp * HH + lane * 8;
    float4 h0 = *(const float4*)hr;
    float4 h1 = *(const float4*)(hr + 4);
    float4 p0 = *(const float4*)(a1 + lane * 8);
    float4 p1 = *(const float4*)(a1 + lane * 8 + 4);
    float4 q0 = *(const float4*)(a2 + lane * 8);
    float4 q1 = *(const float4*)(a2 + lane * 8 + 4);

    float d1 = h0.x * p0.x + h0.y * p0.y + h0.z * p0.z + h0.w * p0.w +
               h1.x * p1.x + h1.y * p1.y + h1.z * p1.z + h1.w * p1.w;
    float d2 = h0.x * q0.x + h0.y * q0.y + h0.z * q0.z + h0.w * q0.w +
               h1.x * q1.x + h1.y * q1.y + h1.z * q1.z + h1.w * q1.w;
#pragma unroll
    for (int off = 16; off; off >>= 1) {
        d1 += __shfl_xor_sync(0xffffffffu, d1, off);
        d2 += __shfl_xor_sync(0xffffffffu, d2, off);
    }
    if (lane == 0) {
        g_s1[warp] = d1;
        g_s2[warp] = d2;
    }
}

// ---------------- softmax stats per row: m, 1/l (one warp per row) ---------
__global__ void stats_kernel(const float* __restrict__ adj)
{
    int warp_in = threadIdx.x >> 5;
    int lane = threadIdx.x & 31;
    int row = blockIdx.x * 8 + warp_in;           // row in [0, BB*NN)
    int b = row >> 10;

    const float* ar = adj + (size_t)row * NN;
    const float* s2b = g_s2 + (b << 10);
    float s1v = g_s1[row];

    float e[32];
    float m = -INFINITY;
#pragma unroll
    for (int jj = 0; jj < 32; jj++) {
        int j = jj * 32 + lane;
        float a = ar[j];
        float t = s1v + s2b[j];
        t = (t >= 0.f) ? t : LALPHA * t;
        t = (a > 0.f) ? t : NEGV;
        e[jj] = t;
        m = fmaxf(m, t);
    }
#pragma unroll
    for (int off = 16; off; off >>= 1)
        m = fmaxf(m, __shfl_xor_sync(0xffffffffu, m, off));

    float l = 0.f;
#pragma unroll
    for (int jj = 0; jj < 32; jj++) l += __expf(e[jj] - m);
#pragma unroll
    for (int off = 16; off; off >>= 1)
        l += __shfl_xor_sync(0xffffffffu, l, off);

    if (lane == 0) {
        g_m[row] = m;
        g_linv[row] = 1.f / l;
    }
}

// ---------------- attention: out = relu( softmax(masked e) @ h ) -----------
// One block per (b, 64-row tile). C tile 64x256, P tiles 64x64 computed on
// the fly from adj/s1/s2/m. Epilogue folds 1/l and ReLU.
__global__ void __launch_bounds__(256, 2) attn_kernel(
    const float* __restrict__ adj, const float* __restrict__ h,
    float* __restrict__ out)
{
    int blk = blockIdx.x;          // 0..255
    int b = blk >> 4;
    int i0 = (blk & 15) << 6;

    int tid = threadIdx.x;
    int tx = tid & 15;             // col group: 16 cols
    int ty = tid >> 4;             // row group: 4 rows

    __shared__ float Pt[64][64];   // [k][row]
    __shared__ float Hs[8][HH];
    __shared__ float s1s[64], ms[64], s2s[64];

    if (tid < 64) {
        s1s[tid] = g_s1[b * NN + i0 + tid];
        ms[tid] = g_m[b * NN + i0 + tid];
    }

    float acc[4][16];
#pragma unroll
    for (int r = 0; r < 4; r++)
#pragma unroll
        for (int c = 0; c < 16; c++) acc[r][c] = 0.f;

    const float* adjb = adj + ((size_t)b * NN + i0) * NN;
    const float* hb = h + (size_t)b * NN * HH;

    for (int j0 = 0; j0 < NN; j0 += 64) {
        __syncthreads();               // protect s2s/Pt from previous iter
        if (tid < 64) s2s[tid] = g_s2[b * NN + j0 + tid];
        __syncthreads();

        // build P^T tile: Pt[c][r] = mask ? exp(leaky(s1_r+s2_c) - m_r) : 0
#pragma unroll
        for (int t = 0; t < 4; t++) {
            int lin = tid + t * 256;   // 0..1023
            int r = lin >> 4;          // 0..63
            int c4 = (lin & 15) << 2;  // 0..60
            float4 av = *(const float4*)(adjb + (size_t)r * NN + j0 + c4);
            float sv = s1s[r], mv = ms[r];
            float e0 = sv + s2s[c4 + 0]; e0 = (e0 >= 0.f) ? e0 : LALPHA * e0;
            float e1 = sv + s2s[c4 + 1]; e1 = (e1 >= 0.f) ? e1 : LALPHA * e1;
            float e2 = sv + s2s[c4 + 2]; e2 = (e2 >= 0.f) ? e2 : LALPHA * e2;
            float e3 = sv + s2s[c4 + 3]; e3 = (e3 >= 0.f) ? e3 : LALPHA * e3;
            Pt[c4 + 0][r] = (av.x > 0.f) ? __expf(e0 - mv) : 0.f;
            Pt[c4 + 1][r] = (av.y > 0.f) ? __expf(e1 - mv) : 0.f;
            Pt[c4 + 2][r] = (av.z > 0.f) ? __expf(e2 - mv) : 0.f;
            Pt[c4 + 3][r] = (av.w > 0.f) ? __expf(e3 - mv) : 0.f;
        }
        __syncthreads();

#pragma unroll
        for (int k0 = 0; k0 < 64; k0 += 8) {
            // load H chunk 8x256
#pragma unroll
            for (int t = 0; t < 2; t++) {
                int lin = tid + t * 256;   // 0..511
                int r = lin >> 6;          // 0..7
                int c4 = (lin & 63) << 2;  // 0..252
                *(float4*)&Hs[r][c4] =
                    *(const float4*)(hb + (size_t)(j0 + k0 + r) * HH + c4);
            }
            __syncthreads();
#pragma unroll
            for (int k = 0; k < 8; k++) {
                float4 pa = *(float4*)&Pt[k0 + k][ty * 4];
                float4 b0 = *(float4*)&Hs[k][tx * 16];
                float4 b1 = *(float4*)&Hs[k][tx * 16 + 4];
                float4 b2 = *(float4*)&Hs[k][tx * 16 + 8];
                float4 b3 = *(float4*)&Hs[k][tx * 16 + 12];
                float pav[4] = {pa.x, pa.y, pa.z, pa.w};
                float bv[16] = {b0.x, b0.y, b0.z, b0.w,
                                b1.x, b1.y, b1.z, b1.w,
                                b2.x, b2.y, b2.z, b2.w,
                                b3.x, b3.y, b3.z, b3.w};
#pragma unroll
                for (int r = 0; r < 4; r++)
#pragma unroll
                    for (int c = 0; c < 16; c++)
                        acc[r][c] = fmaf(pav[r], bv[c], acc[r][c]);
            }
            __syncthreads();
        }
    }

    // epilogue: * (1/l), ReLU, store
#pragma unroll
    for (int r = 0; r < 4; r++) {
        int row = i0 + ty * 4 + r;
        float li = g_linv[b * NN + row];
        float* op = out + ((size_t)b * NN + row) * HH + tx * 16;
#pragma unroll
        for (int c = 0; c < 16; c += 4) {
            float4 v;
            v.x = fmaxf(acc[r][c + 0] * li, 0.f);
            v.y = fmaxf(acc[r][c + 1] * li, 0.f);
            v.z = fmaxf(acc[r][c + 2] * li, 0.f);
            v.w = fmaxf(acc[r][c + 3] * li, 0.f);
            *(float4*)(op + c) = v;
        }
    }
}

// ---------------- pooling -------------------------------------------------
__global__ void zero_pool_kernel()
{
    int i = blockIdx.x * blockDim.x + threadIdx.x;
    if (i < BB * HH) {
        g_sum[i] = 0.f;
        g_max[i] = 0.f;   // x >= 0 after ReLU, so 0 is a valid max identity
    }
}

__global__ void pool_kernel(const float* __restrict__ x)
{
    int b = blockIdx.x >> 3;
    int seg = blockIdx.x & 7;
    int t = threadIdx.x;   // 0..255 = feature
    const float* xb = x + ((size_t)b * NN + seg * 128) * HH + t;
    float s = 0.f, mx = 0.f;
#pragma unroll 4
    for (int i = 0; i < 128; i++) {
        float v = xb[(size_t)i * HH];
        s += v;
        mx = fmaxf(mx, v);
    }
    atomicAdd(&g_sum[b * HH + t], s);
    atomicMax((int*)&g_max[b * HH + t], __float_as_int(mx));
}

// ---------------- tiny 2-layer MLP on pooled features ----------------------
__global__ void mlp_kernel(const float* __restrict__ W1,
                           const float* __restrict__ b1,
                           const float* __restrict__ W2,
                           const float* __restrict__ b2,
                           float* __restrict__ gout)
{
    __shared__ float p[HH];
    __shared__ float y1[HH];
    int b = blockIdx.x, t = threadIdx.x;

    p[t] = g_sum[b * HH + t] * (1.f / (float)NN) + g_max[b * HH + t];
    __syncthreads();

    float acc = b1[t];
#pragma unroll 4
    for (int k = 0; k < HH; k++)
        acc = fmaf(p[k], W1[(size_t)k * HH + t], acc);
    y1[t] = fmaxf(acc, 0.f);
    __syncthreads();

    float acc2 = b2[t];
#pragma unroll 4
    for (int k = 0; k < HH; k++)
        acc2 = fmaf(y1[k], W2[(size_t)k * HH + t], acc2);
    gout[b * HH + t] = acc2;
}

// ---------------- launch --------------------------------------------------
extern "C" void kernel_launch(void* const* d_in, const int* in_sizes, int n_in,
                              void* d_out, int out_size)
{
    const float* nf   = (const float*)d_in[0];
    const float* adj  = (const float*)d_in[1];
    const float* embW = (const float*)d_in[2];
    const float* embb = (const float*)d_in[3];
    const float* W0   = (const float*)d_in[4];
    const float* a10  = (const float*)d_in[5];
    const float* a20  = (const float*)d_in[6];
    const float* W1   = (const float*)d_in[7];
    const float* a11  = (const float*)d_in[8];
    const float* a21  = (const float*)d_in[9];
    const float* gW1  = (const float*)d_in[10];
    const float* gb1  = (const float*)d_in[11];
    const float* gW2  = (const float*)d_in[12];
    const float* gb2  = (const float*)d_in[13];

    float* outx = (float*)d_out;
    float* outg = outx + (size_t)BB * NN * HH;

    float *xp = nullptr, *hp = nullptr;
    cudaGetSymbolAddress((void**)&xp, g_x);
    cudaGetSymbolAddress((void**)&hp, g_h);

    const int M = BB * NN;
    dim3 gemm_grid(HH / 64, M / 128);

    // embed: x = nf @ embW + embb
    sgemm_kernel<<<gemm_grid, 256>>>(nf, embW, embb, xp, M, FIN, HH);

    // ---- GAT layer 0 ----
    sgemm_kernel<<<gemm_grid, 256>>>(xp, W0, nullptr, hp, M, HH, HH);
    rowdot_kernel<<<M / 8, 256>>>(hp, a10, a20);
    stats_kernel<<<M / 8, 256>>>(adj);
    attn_kernel<<<BB * (NN / 64), 256>>>(adj, hp, xp);

    // ---- GAT layer 1 ----
    sgemm_kernel<<<gemm_grid, 256>>>(xp, W1, nullptr, hp, M, HH, HH);
    rowdot_kernel<<<M / 8, 256>>>(hp, a11, a21);
    stats_kernel<<<M / 8, 256>>>(adj);
    attn_kernel<<<BB * (NN / 64), 256>>>(adj, hp, outx);

    // ---- pooling + MLP ----
    zero_pool_kernel<<<(BB * HH + 255) / 256, 256>>>();
    pool_kernel<<<BB * 8, 256>>>(outx);
    mlp_kernel<<<BB, 256>>>(gW1, gb1, gW2, gb2, outg);
}